// round 12
// baseline (speedup 1.0000x reference)
#include <cuda_runtime.h>

#define N_NODES 50000
#define N_EDGES 800000
#define DIM 64
#define NLAYERS 3
#define LN_EPS 1e-5f

// ---------------- device scratch (no allocations allowed) ----------------
__device__ float g_bufA[(size_t)N_NODES * DIM];
__device__ float g_bufB[(size_t)N_NODES * DIM];
__device__ int   g_deg[N_NODES];
__device__ int   g_rowptr[N_NODES + 1];
__device__ int   g_cursor[N_NODES];
__device__ int2  g_edge[N_EDGES];    // .x = src node, .y = bitcast(norm weight)
__device__ float g_dinv[N_NODES];

// ---------------- CSR construction ----------------
__global__ void zero_deg_kernel() {
    int i = blockIdx.x * blockDim.x + threadIdx.x;
    if (i < N_NODES) g_deg[i] = 0;
}

// 4 edges per thread via int4 loads for MLP on the atomic path.
__global__ void hist_kernel(const int* __restrict__ dst) {
    int t = blockIdx.x * blockDim.x + threadIdx.x;
    int e = t * 4;
    if (e + 4 <= N_EDGES) {
        int4 d4 = __ldg((const int4*)(dst + e));
        atomicAdd(&g_deg[d4.x], 1);
        atomicAdd(&g_deg[d4.y], 1);
        atomicAdd(&g_deg[d4.z], 1);
        atomicAdd(&g_deg[d4.w], 1);
    } else {
        for (int i = e; i < N_EDGES; i++) atomicAdd(&g_deg[__ldg(dst + i)], 1);
    }
}

// Single-block exclusive scan over 50k degrees + dinv computation.
__global__ void scan_kernel() {
    __shared__ int ssum[1024];
    const int CH = (N_NODES + 1023) / 1024;  // 49
    int t = threadIdx.x;
    int base = t * CH;
    int sum = 0;
    for (int i = 0; i < CH; i++) {
        int idx = base + i;
        if (idx < N_NODES) sum += g_deg[idx];
    }
    ssum[t] = sum;
    __syncthreads();
    for (int off = 1; off < 1024; off <<= 1) {
        int v = (t >= off) ? ssum[t - off] : 0;
        __syncthreads();
        ssum[t] += v;
        __syncthreads();
    }
    int run = ssum[t] - sum;  // exclusive prefix of this chunk
    for (int i = 0; i < CH; i++) {
        int idx = base + i;
        if (idx < N_NODES) {
            int d = g_deg[idx];
            g_rowptr[idx] = run;
            g_cursor[idx] = run;
            g_dinv[idx]   = rsqrtf((float)(d + 1));  // +1 self-loop
            run += d;
        }
    }
    if (t == 0) g_rowptr[N_NODES] = N_EDGES;
}

__global__ void fill_csr_kernel(const int* __restrict__ src,
                                const int* __restrict__ dst) {
    int t = blockIdx.x * blockDim.x + threadIdx.x;
    int e = t * 4;
    if (e + 4 <= N_EDGES) {
        int4 s4 = __ldg((const int4*)(src + e));
        int4 d4 = __ldg((const int4*)(dst + e));
        float ds0 = __ldg(g_dinv + s4.x), dd0 = __ldg(g_dinv + d4.x);
        float ds1 = __ldg(g_dinv + s4.y), dd1 = __ldg(g_dinv + d4.y);
        float ds2 = __ldg(g_dinv + s4.z), dd2 = __ldg(g_dinv + d4.z);
        float ds3 = __ldg(g_dinv + s4.w), dd3 = __ldg(g_dinv + d4.w);
        int p0 = atomicAdd(&g_cursor[d4.x], 1);
        int p1 = atomicAdd(&g_cursor[d4.y], 1);
        int p2 = atomicAdd(&g_cursor[d4.z], 1);
        int p3 = atomicAdd(&g_cursor[d4.w], 1);
        g_edge[p0] = make_int2(s4.x, __float_as_int(ds0 * dd0));
        g_edge[p1] = make_int2(s4.y, __float_as_int(ds1 * dd1));
        g_edge[p2] = make_int2(s4.z, __float_as_int(ds2 * dd2));
        g_edge[p3] = make_int2(s4.w, __float_as_int(ds3 * dd3));
    } else {
        for (int i = e; i < N_EDGES; i++) {
            int s = __ldg(src + i);
            int d = __ldg(dst + i);
            int pos = atomicAdd(&g_cursor[d], 1);
            g_edge[pos] = make_int2(s, __float_as_int(__ldg(g_dinv + s) * __ldg(g_dinv + d)));
        }
    }
}

// ---------------- fused layer: aggregate(X) -> @W -> +bias -> LN -> ReLU ----
// One warp per node; lane owns cols [2*lane, 2*lane+1].
// No SHFL on any critical path: edge records (idx, w) packed 8B, read via
// warp-uniform LDG (hardware broadcast); GEMM broadcast via smem staging.
#define NPW 4           // nodes per warp
#define LTHREADS 512    // 16 warps per block
__global__ void __launch_bounds__(LTHREADS)
layer_kernel(const float* __restrict__ Pin,
             const float* __restrict__ W,
             const float* __restrict__ bias,
             const float* __restrict__ gamma,
             const float* __restrict__ beta,
             float* __restrict__ Qout) {
    __shared__ float sW[DIM * DIM];
    __shared__ float sAcc[LTHREADS / 32][DIM];
    int tid = threadIdx.x;
    for (int idx = tid; idx < DIM * DIM; idx += LTHREADS) sW[idx] = W[idx];
    __syncthreads();

    int lane = tid & 31;
    int warp = tid >> 5;
    const float2* __restrict__ P2 = (const float2*)Pin;
    const float2* sW2 = (const float2*)sW;
    float* myAcc = sAcc[warp];

    // per-lane layer constants
    float b0  = bias[2 * lane],  b1  = bias[2 * lane + 1];
    float ga0 = gamma[2 * lane], ga1 = gamma[2 * lane + 1];
    float be0 = beta[2 * lane],  be1 = beta[2 * lane + 1];

    int nodeBase = (blockIdx.x * (LTHREADS / 32) + warp) * NPW;

    #pragma unroll
    for (int r = 0; r < NPW; r++) {
        int node = nodeBase + r;
        if (node >= N_NODES) return;

        // ---- normalized aggregation of previous activations ----
        float di = g_dinv[node];
        float2 xs = __ldg(P2 + (size_t)node * (DIM / 2) + lane);
        float sl = di * di;
        float accx = sl * xs.x;
        float accy = sl * xs.y;

        int s0 = __ldg(g_rowptr + node);
        int s1 = __ldg(g_rowptr + node + 1);
        int e  = s0;
        // 4-way unrolled gather: edge records are warp-uniform 8B LDGs
        // (1 broadcast wavefront each); 8 loads in flight before any FMA.
        for (; e + 4 <= s1; e += 4) {
            int2 e0 = __ldg(g_edge + e);
            int2 e1 = __ldg(g_edge + e + 1);
            int2 e2 = __ldg(g_edge + e + 2);
            int2 e3 = __ldg(g_edge + e + 3);
            float2 v0 = __ldg(P2 + (size_t)e0.x * (DIM / 2) + lane);
            float2 v1 = __ldg(P2 + (size_t)e1.x * (DIM / 2) + lane);
            float2 v2 = __ldg(P2 + (size_t)e2.x * (DIM / 2) + lane);
            float2 v3 = __ldg(P2 + (size_t)e3.x * (DIM / 2) + lane);
            float w0 = __int_as_float(e0.y);
            float w1 = __int_as_float(e1.y);
            float w2 = __int_as_float(e2.y);
            float w3 = __int_as_float(e3.y);
            accx = fmaf(w0, v0.x, accx); accy = fmaf(w0, v0.y, accy);
            accx = fmaf(w1, v1.x, accx); accy = fmaf(w1, v1.y, accy);
            accx = fmaf(w2, v2.x, accx); accy = fmaf(w2, v2.y, accy);
            accx = fmaf(w3, v3.x, accx); accy = fmaf(w3, v3.y, accy);
        }
        for (; e < s1; e++) {
            int2 e0 = __ldg(g_edge + e);
            float2 v0 = __ldg(P2 + (size_t)e0.x * (DIM / 2) + lane);
            float w0 = __int_as_float(e0.y);
            accx = fmaf(w0, v0.x, accx);
            accy = fmaf(w0, v0.y, accy);
        }

        // ---- stage aggregated row in smem, then 1x64 @ 64x64 transform ----
        ((float2*)myAcc)[lane] = make_float2(accx, accy);
        __syncwarp();
        float ox = 0.f, oy = 0.f;
        #pragma unroll
        for (int k = 0; k < DIM; k++) {
            float ak = myAcc[k];                 // broadcast LDS, conflict-free
            float2 w2 = sW2[k * 32 + lane];
            ox = fmaf(ak, w2.x, ox);
            oy = fmaf(ak, w2.y, oy);
        }
        __syncwarp();

        ox += b0;
        oy += b1;

        // ---- LayerNorm over 64 features (warp reduction) + ReLU ----
        float s  = ox + oy;
        float sq = ox * ox + oy * oy;
        #pragma unroll
        for (int o = 16; o; o >>= 1) {
            s  += __shfl_xor_sync(0xffffffffu, s,  o);
            sq += __shfl_xor_sync(0xffffffffu, sq, o);
        }
        float mu   = s * (1.0f / DIM);
        float var  = sq * (1.0f / DIM) - mu * mu;
        float rstd = rsqrtf(var + LN_EPS);
        float y0 = fmaxf((ox - mu) * rstd * ga0 + be0, 0.f);
        float y1 = fmaxf((oy - mu) * rstd * ga1 + be1, 0.f);
        ((float2*)(Qout + (size_t)node * DIM))[lane] = make_float2(y0, y1);
    }
}

// ---------------- launch ----------------
extern "C" void kernel_launch(void* const* d_in, const int* in_sizes, int n_in,
                              void* d_out, int out_size) {
    const float* x     = (const float*)d_in[0];
    const int*   ei    = (const int*)  d_in[1];   // [2, E] row-major
    const float* Ws    = (const float*)d_in[2];   // [3, 64, 64]
    const float* bs    = (const float*)d_in[3];   // [3, 64]
    const float* gs    = (const float*)d_in[4];   // [3, 64]
    const float* betas = (const float*)d_in[5];   // [3, 64]
    const int* srcp = ei;
    const int* dstp = ei + N_EDGES;
    float* out = (float*)d_out;

    const int e4_blocks = (N_EDGES / 4 + 255) / 256;
    zero_deg_kernel<<<(N_NODES + 255) / 256, 256>>>();
    hist_kernel<<<e4_blocks, 256>>>(dstp);
    scan_kernel<<<1, 1024>>>();
    fill_csr_kernel<<<e4_blocks, 256>>>(srcp, dstp);

    const int nodes_per_block = (LTHREADS / 32) * NPW;  // 64
    const int layer_blocks = (N_NODES + nodes_per_block - 1) / nodes_per_block;

    float* bufA; cudaGetSymbolAddress((void**)&bufA, g_bufA);
    float* bufB; cudaGetSymbolAddress((void**)&bufB, g_bufB);

    layer_kernel<<<layer_blocks, LTHREADS>>>(x,    Ws,                 bs,          gs,          betas,          bufA);
    layer_kernel<<<layer_blocks, LTHREADS>>>(bufA, Ws + DIM * DIM,     bs + DIM,    gs + DIM,    betas + DIM,    bufB);
    layer_kernel<<<layer_blocks, LTHREADS>>>(bufB, Ws + 2 * DIM * DIM, bs + 2*DIM,  gs + 2*DIM,  betas + 2*DIM,  out);
}

// round 16
// speedup vs baseline: 1.4451x; 1.4451x over previous
#include <cuda_runtime.h>

#define N_NODES 50000
#define N_EDGES 800000
#define DIM 64
#define NLAYERS 3
#define LN_EPS 1e-5f

// ---------------- device scratch (no allocations allowed) ----------------
__device__ float g_h[(size_t)N_NODES * DIM];    // per-layer GEMM output
__device__ float g_buf[(size_t)N_NODES * DIM];  // layer activations ping buffer
__device__ int   g_deg[N_NODES];
__device__ int   g_rowptr[N_NODES + 1];
__device__ int   g_cursor[N_NODES];
__device__ int2  g_edge[N_EDGES];    // .x = src node, .y = bitcast(dinv[src]*dinv[dst])
__device__ float g_dinv[N_NODES];

// ---------------- CSR construction (1 edge/thread: empirically fastest) ----
__global__ void zero_deg_kernel() {
    int i = blockIdx.x * blockDim.x + threadIdx.x;
    if (i < N_NODES) g_deg[i] = 0;
}

__global__ void hist_kernel(const int* __restrict__ dst) {
    int e = blockIdx.x * blockDim.x + threadIdx.x;
    if (e < N_EDGES) atomicAdd(&g_deg[__ldg(dst + e)], 1);
}

// Single-block exclusive scan over 50k degrees + dinv computation.
__global__ void scan_kernel() {
    __shared__ int ssum[1024];
    const int CH = (N_NODES + 1023) / 1024;  // 49
    int t = threadIdx.x;
    int base = t * CH;
    int sum = 0;
    for (int i = 0; i < CH; i++) {
        int idx = base + i;
        if (idx < N_NODES) sum += g_deg[idx];
    }
    ssum[t] = sum;
    __syncthreads();
    for (int off = 1; off < 1024; off <<= 1) {
        int v = (t >= off) ? ssum[t - off] : 0;
        __syncthreads();
        ssum[t] += v;
        __syncthreads();
    }
    int run = ssum[t] - sum;  // exclusive prefix of this chunk
    for (int i = 0; i < CH; i++) {
        int idx = base + i;
        if (idx < N_NODES) {
            int d = g_deg[idx];
            g_rowptr[idx] = run;
            g_cursor[idx] = run;
            g_dinv[idx]   = rsqrtf((float)(d + 1));  // +1 self-loop
            run += d;
        }
    }
    if (t == 0) g_rowptr[N_NODES] = N_EDGES;
}

__global__ void fill_csr_kernel(const int* __restrict__ src,
                                const int* __restrict__ dst) {
    int e = blockIdx.x * blockDim.x + threadIdx.x;
    if (e < N_EDGES) {
        int s = __ldg(src + e);
        int d = __ldg(dst + e);
        float w = __ldg(g_dinv + s) * __ldg(g_dinv + d);
        int pos = atomicAdd(&g_cursor[d], 1);
        g_edge[pos] = make_int2(s, __float_as_int(w));
    }
}

// ---------------- dense transform: g_h = X @ W (proven R4 kernel) ----------
#define ROWS_PER_WARP 4
__global__ void gemm64_kernel(const float* __restrict__ Xext, int use_ext,
                              const float* __restrict__ W) {
    __shared__ float sW[DIM * DIM];
    const float* __restrict__ X = use_ext ? Xext : (const float*)g_buf;
    int tid = threadIdx.x;
    for (int idx = tid; idx < DIM * DIM; idx += 256) sW[idx] = W[idx];
    __syncthreads();

    int lane = tid & 31;
    int warp = tid >> 5;
    int rowBase = (blockIdx.x * 8 + warp) * ROWS_PER_WARP;
    const float2* sW2 = (const float2*)sW;

    #pragma unroll
    for (int r = 0; r < ROWS_PER_WARP; r++) {
        int row = rowBase + r;
        if (row >= N_NODES) return;
        float2 xv = __ldg((const float2*)(X + (size_t)row * DIM) + lane);
        float accx = 0.f, accy = 0.f;
        #pragma unroll
        for (int k = 0; k < DIM; k++) {
            float xk = __shfl_sync(0xffffffffu, (k & 1) ? xv.y : xv.x, k >> 1);
            float2 w = sW2[k * 32 + lane];
            accx = fmaf(xk, w.x, accx);
            accy = fmaf(xk, w.y, accy);
        }
        ((float2*)(g_h + (size_t)row * DIM))[lane] = make_float2(accx, accy);
    }
}

// ---------------- fused aggregate + bias + LayerNorm + ReLU ----------------
// One warp per node (R4 structure). Coalesced 32-edge packed-record load,
// shfl broadcast, gather pipeline depth 3 (two row loads in flight).
__global__ void agg_ln_relu_kernel(const float* __restrict__ bias,
                                   const float* __restrict__ gamma,
                                   const float* __restrict__ beta,
                                   float* __restrict__ out_ext, int use_ext) {
    int gw = (blockIdx.x * blockDim.x + threadIdx.x) >> 5;
    int lane = threadIdx.x & 31;
    if (gw >= N_NODES) return;
    float* out = use_ext ? out_ext : g_buf;
    const float2* __restrict__ H2 = (const float2*)g_h;

    int s0 = __ldg(g_rowptr + gw);
    int s1 = __ldg(g_rowptr + gw + 1);
    float di = g_dinv[gw];
    float2 hv = __ldg(H2 + (size_t)gw * (DIM / 2) + lane);
    float sl = di * di;  // self-loop norm
    float accx = sl * hv.x;
    float accy = sl * hv.y;

    for (int b = s0; b < s1; b += 32) {
        int n = s1 - b;
        if (n > 32) n = 32;
        int2 er = make_int2(0, 0);
        if (lane < n) er = __ldg(g_edge + b + lane);  // one coalesced 256B load

        // depth-3 software pipeline: v0 (edge k), v1 (edge k+1) in flight
        float2 v0 = make_float2(0.f, 0.f), v1 = make_float2(0.f, 0.f);
        float  w0 = 0.f, w1 = 0.f;
        {
            int   s = __shfl_sync(0xffffffffu, er.x, 0);
            w0 = __int_as_float(__shfl_sync(0xffffffffu, er.y, 0));
            v0 = __ldg(H2 + (size_t)s * (DIM / 2) + lane);
        }
        if (n > 1) {
            int   s = __shfl_sync(0xffffffffu, er.x, 1);
            w1 = __int_as_float(__shfl_sync(0xffffffffu, er.y, 1));
            v1 = __ldg(H2 + (size_t)s * (DIM / 2) + lane);
        }
        for (int k = 0; k < n; k++) {
            float2 vc = v0;
            float  wc = w0;
            v0 = v1; w0 = w1;
            if (k + 2 < n) {
                int s = __shfl_sync(0xffffffffu, er.x, k + 2);
                w1 = __int_as_float(__shfl_sync(0xffffffffu, er.y, k + 2));
                v1 = __ldg(H2 + (size_t)s * (DIM / 2) + lane);
            }
            accx = fmaf(wc, vc.x, accx);
            accy = fmaf(wc, vc.y, accy);
        }
    }

    accx += bias[2 * lane];
    accy += bias[2 * lane + 1];

    // LayerNorm over 64 features via warp reduction
    float s  = accx + accy;
    float sq = accx * accx + accy * accy;
    #pragma unroll
    for (int o = 16; o; o >>= 1) {
        s  += __shfl_xor_sync(0xffffffffu, s,  o);
        sq += __shfl_xor_sync(0xffffffffu, sq, o);
    }
    float mu   = s * (1.0f / DIM);
    float var  = sq * (1.0f / DIM) - mu * mu;
    float rstd = rsqrtf(var + LN_EPS);
    float y0 = (accx - mu) * rstd * gamma[2 * lane]     + beta[2 * lane];
    float y1 = (accy - mu) * rstd * gamma[2 * lane + 1] + beta[2 * lane + 1];
    y0 = fmaxf(y0, 0.f);
    y1 = fmaxf(y1, 0.f);
    ((float2*)(out + (size_t)gw * DIM))[lane] = make_float2(y0, y1);
}

// ---------------- launch ----------------
extern "C" void kernel_launch(void* const* d_in, const int* in_sizes, int n_in,
                              void* d_out, int out_size) {
    const float* x     = (const float*)d_in[0];
    const int*   ei    = (const int*)  d_in[1];   // [2, E] row-major
    const float* Ws    = (const float*)d_in[2];   // [3, 64, 64]
    const float* bs    = (const float*)d_in[3];   // [3, 64]
    const float* gs    = (const float*)d_in[4];   // [3, 64]
    const float* betas = (const float*)d_in[5];   // [3, 64]
    const int* srcp = ei;
    const int* dstp = ei + N_EDGES;
    float* out = (float*)d_out;

    zero_deg_kernel<<<(N_NODES + 255) / 256, 256>>>();
    hist_kernel<<<(N_EDGES + 255) / 256, 256>>>(dstp);
    scan_kernel<<<1, 1024>>>();
    fill_csr_kernel<<<(N_EDGES + 255) / 256, 256>>>(srcp, dstp);

    const int gemm_blocks = (N_NODES + 8 * ROWS_PER_WARP - 1) / (8 * ROWS_PER_WARP);
    const int agg_blocks  = (N_NODES * 32 + 255) / 256;

    for (int l = 0; l < NLAYERS; l++) {
        gemm64_kernel<<<gemm_blocks, 256>>>(x, l == 0 ? 1 : 0, Ws + l * DIM * DIM);
        agg_ln_relu_kernel<<<agg_blocks, 256>>>(bs + l * DIM, gs + l * DIM,
                                                betas + l * DIM,
                                                out, l == NLAYERS - 1 ? 1 : 0);
    }
}